// round 9
// baseline (speedup 1.0000x reference)
#include <cuda_runtime.h>
#include <cstdint>

// EngramGating: B=16, S=16384, DIM=32, H=4  (T = 262144 tokens)
// out[t,h,k] = sigmoid(signed_sqrt(gate_raw[t,h])) * (emb[t] @ Wv^T + bv)[k]
// gate_raw[t,h] = sum_k( rms(key)*g1 * rms(q)*g2 ) / sqrt(32)
// key[t,h,k] = sum_d emb[t,d] * Wk[h,k,d] + bk[h,k]
//
// R9 = R5 (121.3us) + LDS.128 weight/e loads (swizzled per-k chunk rows),
//      smem value redistribution (replaces 4x shfl.idx), 4 blocks/SM.

#define DIM 32
#define HC  4
#define TTOK 8
#define WARPS_PER_BLOCK 4
#define THREADS (WARPS_PER_BLOCK * 32)
#define GRID_BLOCKS 592            // 148 SMs * 4 blocks -> one wave

__device__ __forceinline__ void fma2(unsigned long long& acc,
                                     unsigned long long a,
                                     unsigned long long b) {
    asm("fma.rn.f32x2 %0, %1, %2, %0;" : "+l"(acc) : "l"(a), "l"(b));
}

__device__ __forceinline__ float hadd2(unsigned long long v) {
    return __uint_as_float((unsigned)v) + __uint_as_float((unsigned)(v >> 32));
}

__global__ void __launch_bounds__(THREADS, 4)
engram_gating_kernel(const float* __restrict__ emb,      // [T,32]
                     const float* __restrict__ hid,      // [T,4,32]
                     const float* __restrict__ Wv,       // [32,32]
                     const float* __restrict__ bv,       // [32]
                     const float* __restrict__ Wk,       // [4,32,32]
                     const float* __restrict__ bk,       // [4,32]
                     const float* __restrict__ g1,       // [4,32]
                     const float* __restrict__ g2,       // [4,32]
                     float* __restrict__ out,            // [T,4,32]
                     int nTok) {
    // Weights as 16B chunks: row k holds 8 chunks (chunk dp2 = d-pairs 2dp2,2dp2+1).
    // Wk chunk column swizzle: dp2 ^ ((k>>2)&7)  (read lanes have k=4i+c -> k>>2=i, distinct/phase)
    // Wv chunk column swizzle: dp2 ^ (k&7)       (read lanes have k=lane, distinct/phase)
    __shared__ ulonglong2 sWk4[HC][32][8];     // 16 KB
    __shared__ ulonglong2 sWv4[32][8];         //  4 KB
    __shared__ ulonglong2 sE4[WARPS_PER_BLOCK][TTOK][8];   // 4 KB (e chunks, broadcast-read)
    __shared__ float sVal[WARPS_PER_BLOCK][TTOK][32];      // 4 KB (value redistribution)
    __shared__ float sBk[HC][32];
    __shared__ float sGG[HC][32];
    __shared__ float sBv[32];

    const int tid = threadIdx.x;

    // ---- stage weights (once per block) ----
    {
        const ulonglong2* WkU = (const ulonglong2*)Wk;   // 1024 chunks
        for (int j = tid; j < HC * 32 * 8; j += THREADS) {
            int h = j >> 8, k = (j >> 3) & 31, dp2 = j & 7;
            sWk4[h][k][dp2 ^ ((k >> 2) & 7)] = WkU[j];
        }
        const ulonglong2* WvU = (const ulonglong2*)Wv;   // 256 chunks
        for (int j = tid; j < 32 * 8; j += THREADS) {
            int k = j >> 3, dp2 = j & 7;
            sWv4[k][dp2 ^ (k & 7)] = WvU[j];
        }
        for (int i = tid; i < HC * 32; i += THREADS) {
            ((float*)sBk)[i] = bk[i];
            ((float*)sGG)[i] = g1[i] * g2[i];
        }
        if (tid < 32) sBv[tid] = bv[tid];
    }
    __syncthreads();

    const int lane = tid & 31;
    const int w = tid >> 5;
    const int hH = lane >> 3;          // head of this lane
    const int iI = lane & 7;           // index within 8-lane group

    // ---- per-lane constants ----
    float bkc[4], ggc[4];
#pragma unroll
    for (int c = 0; c < 4; c++) {
        bkc[c] = sBk[hH][4 * iI + c];
        ggc[c] = sGG[hH][4 * iI + c];
    }
    const float bvl = sBv[lane];
    const int vsw = lane & 7;          // Wv column swizzle for this lane (k=lane)

    const int warpG = blockIdx.x * WARPS_PER_BLOCK + w;
    const int nWarps = gridDim.x * WARPS_PER_BLOCK;
    const int nGroups = (nTok + TTOK - 1) / TTOK;

    const float EPS = 1.1920929e-07f;
    const float INV32 = 0.03125f;
    const float INVSQRT32 = 0.17677669529663687f;

    for (int g = warpG; g < nGroups; g += nWarps) {
        const int tb = g * TTOK;
        const bool full = (tb + TTOK) <= nTok;

        // ---- stage emb for 8 tokens: 2 x LDG.128 per lane -> sE4 chunks ----
        // float4 index f covers token f>>3, chunk f&7.
        if (full) {
            const float4* ep = (const float4*)(emb + (size_t)tb * DIM);
            float4 a = ep[lane], b = ep[32 + lane];
            sE4[w][lane >> 3][lane & 7] = *(ulonglong2*)&a;
            sE4[w][4 + (lane >> 3)][lane & 7] = *(ulonglong2*)&b;
        } else {
            for (int r = 0; r < 2; r++) {
                int f = r * 32 + lane;
                float4 v = make_float4(0.f, 0.f, 0.f, 0.f);
                int base = tb * DIM + f * 4;
                if (base + 3 < nTok * DIM) v = *(const float4*)(emb + base);
                sE4[w][f >> 3][f & 7] = *(ulonglong2*)&v;
            }
        }

        // ---- prefetch q: one float4 per lane per token ----
        float4 qv[TTOK];
#pragma unroll
        for (int t = 0; t < TTOK; t++) {
            int tok = tb + t;
            if (full || tok < nTok)
                qv[t] = *(const float4*)(hid + (size_t)tok * (HC * DIM) + lane * 4);
            else
                qv[t] = make_float4(0.f, 0.f, 0.f, 0.f);
        }

        __syncwarp();

        // ---- mat-vec: 4 keys + value, 8 tokens, LDS.128 + packed FMA2 ----
        unsigned long long acck[TTOK][4];
        unsigned long long accv[TTOK];
#pragma unroll
        for (int t = 0; t < TTOK; t++) {
            accv[t] = 0ull;
#pragma unroll
            for (int c = 0; c < 4; c++) acck[t][c] = 0ull;
        }

#pragma unroll
        for (int dp2 = 0; dp2 < 8; dp2++) {
            const int kcol = dp2 ^ iI;     // Wk swizzled column (same for all 4 c)
            ulonglong2 wv  = sWv4[lane][dp2 ^ vsw];
            ulonglong2 wk0 = sWk4[hH][4 * iI + 0][kcol];
            ulonglong2 wk1 = sWk4[hH][4 * iI + 1][kcol];
            ulonglong2 wk2 = sWk4[hH][4 * iI + 2][kcol];
            ulonglong2 wk3 = sWk4[hH][4 * iI + 3][kcol];
#pragma unroll
            for (int t = 0; t < TTOK; t++) {
                ulonglong2 e = sE4[w][t][dp2];     // broadcast LDS.128
                fma2(accv[t], wv.x, e.x);  fma2(accv[t], wv.y, e.y);
                fma2(acck[t][0], wk0.x, e.x);  fma2(acck[t][0], wk0.y, e.y);
                fma2(acck[t][1], wk1.x, e.x);  fma2(acck[t][1], wk1.y, e.y);
                fma2(acck[t][2], wk2.x, e.x);  fma2(acck[t][2], wk2.y, e.y);
                fma2(acck[t][3], wk3.x, e.x);  fma2(acck[t][3], wk3.y, e.y);
            }
        }

        // ---- publish value (lane=k mapping) to smem for redistribution ----
#pragma unroll
        for (int t = 0; t < TTOK; t++)
            sVal[w][t][lane] = hadd2(accv[t]) + bvl;
        __syncwarp();

        // ---- epilogue per token ----
#pragma unroll
        for (int t = 0; t < TTOK; t++) {
            int tok = tb + t;
            if (full || tok < nTok) {
                float k0 = hadd2(acck[t][0]) + bkc[0];
                float k1 = hadd2(acck[t][1]) + bkc[1];
                float k2 = hadd2(acck[t][2]) + bkc[2];
                float k3 = hadd2(acck[t][3]) + bkc[3];
                float4 q = qv[t];

                float kk = k0 * k0 + k1 * k1 + k2 * k2 + k3 * k3;
                float qq = q.x * q.x + q.y * q.y + q.z * q.z + q.w * q.w;
                float kq = k0 * ggc[0] * q.x + k1 * ggc[1] * q.y
                         + k2 * ggc[2] * q.z + k3 * ggc[3] * q.w;

                // 3-step butterfly in 8-lane groups (serves 4 heads/instr)
#pragma unroll
                for (int m = 1; m < 8; m <<= 1) {
                    kk += __shfl_xor_sync(0xffffffffu, kk, m);
                    qq += __shfl_xor_sync(0xffffffffu, qq, m);
                    kq += __shfl_xor_sync(0xffffffffu, kq, m);
                }

                float r = kq * rsqrtf(fmaf(kk, INV32, EPS))
                             * rsqrtf(fmaf(qq, INV32, EPS)) * INVSQRT32;
                float a = sqrtf(fmaxf(fabsf(r), 1e-6f));
                a = (r > 0.f) ? a : ((r < 0.f) ? -a : 0.f);
                float gate = 1.0f / (1.0f + __expf(-a));

                // value for this lane's 4 k's via smem (conflict-free LDS.128)
                float4 vv = *(const float4*)&sVal[w][t][4 * iI];

                float4 o = make_float4(gate * vv.x, gate * vv.y,
                                       gate * vv.z, gate * vv.w);
                *(float4*)(out + (size_t)tok * (HC * DIM) + lane * 4) = o;
            }
        }
        __syncwarp();   // protect sE4/sVal before next iteration
    }
}

extern "C" void kernel_launch(void* const* d_in, const int* in_sizes, int n_in,
                              void* d_out, int out_size) {
    const float* emb = (const float*)d_in[0];
    const float* hid = (const float*)d_in[1];
    const float* Wv  = (const float*)d_in[2];
    const float* bv  = (const float*)d_in[3];
    const float* Wk  = (const float*)d_in[4];
    const float* bk  = (const float*)d_in[5];
    const float* g1  = (const float*)d_in[6];
    const float* g2  = (const float*)d_in[7];
    float* out = (float*)d_out;

    int nTok = in_sizes[0] / DIM;

    engram_gating_kernel<<<GRID_BLOCKS, THREADS>>>(
        emb, hid, Wv, bv, Wk, bk, g1, g2, out, nTok);
}

// round 10
// speedup vs baseline: 1.9996x; 1.9996x over previous
#include <cuda_runtime.h>
#include <cuda_bf16.h>
#include <cstdint>

// EngramGating via mma.sync (HMMA fallback on sm_103):
//   D[16tok x 160] = A[16 x 32] @ B[32 x 160]   per warp-tile,
//   A = emb rows, B cols: n<128 -> key (h=n>>5, k=n&31), n>=128 -> value row.
//   bf16 3-term split: ehi*Whi + ehi*Wlo + elo*Whi, fp32 accumulate.
// Keys consumed head-sequentially (acc reuse); gates via smem; q via cp.async.

#define HC       4
#define TILE_M   16
#define THREADS  256
#define NWARPS   8
#define NBLOCKS  296            // 148 SMs * 2 blocks

// ---- dynamic smem layout (bytes) ----
#define SB_STRIDE 164           // u64 per fragment-row (164 % 16 == 4 -> conflict-free)
#define OFF_SB    0                               // 16 rows * 164 * 8 = 20992
#define OFF_BK    20992                           // 128 f
#define OFF_GG    21504                           // 128 f
#define OFF_BV    22016                           // 32 f
#define OFF_ES    22144                           // 8 warps * 16*40*4 = 20480
#define ES_W      2560
#define OFF_Q     (OFF_ES + NWARPS * ES_W)        // 42624
#define QW_BYTES  8704                            // 16 rows * 136 f * 4
#define OFF_GATE  (OFF_Q + NWARPS * QW_BYTES)     // 112256 ; 8 * 64 f
#define SMEM_TOTAL (OFF_GATE + NWARPS * 256)      // 114304

__device__ __forceinline__ unsigned su32(const void* p) {
    return (unsigned)__cvta_generic_to_shared(p);
}
__device__ __forceinline__ void cp16(unsigned d, const void* s) {
    asm volatile("cp.async.cg.shared.global [%0], [%1], 16;" :: "r"(d), "l"(s));
}
__device__ __forceinline__ unsigned packhi(float2 p) {
    __nv_bfloat162 h = __floats2bfloat162_rn(p.x, p.y);
    return *(unsigned*)&h;
}
__device__ __forceinline__ unsigned packlo(float2 p) {
    __nv_bfloat162 h = __floats2bfloat162_rn(p.x, p.y);
    float2 hf = __bfloat1622float2(h);
    __nv_bfloat162 l = __floats2bfloat162_rn(p.x - hf.x, p.y - hf.y);
    return *(unsigned*)&l;
}
__device__ __forceinline__ void mma_bf16(float4& d, const unsigned* a,
                                         unsigned b0, unsigned b1) {
    asm volatile(
        "mma.sync.aligned.m16n8k16.row.col.f32.bf16.bf16.f32 "
        "{%0,%1,%2,%3},{%4,%5,%6,%7},{%8,%9},{%0,%1,%2,%3};"
        : "+f"(d.x), "+f"(d.y), "+f"(d.z), "+f"(d.w)
        : "r"(a[0]), "r"(a[1]), "r"(a[2]), "r"(a[3]), "r"(b0), "r"(b1));
}

__global__ void __launch_bounds__(THREADS, 2)
engram_gating_mma(const float* __restrict__ emb,      // [T,32]
                  const float* __restrict__ hid,      // [T,4,32]
                  const float* __restrict__ Wv,       // [32,32]
                  const float* __restrict__ bv,       // [32]
                  const float* __restrict__ Wk,       // [4,32,32]
                  const float* __restrict__ bk,       // [4,32]
                  const float* __restrict__ g1,       // [4,32]
                  const float* __restrict__ g2,       // [4,32]
                  float* __restrict__ out,            // [T,4,32]
                  int nTok) {
    extern __shared__ __align__(16) char sm[];
    unsigned long long* sB = (unsigned long long*)(sm + OFF_SB);
    float* sBK = (float*)(sm + OFF_BK);
    float* sGG = (float*)(sm + OFF_GG);
    float* sBV = (float*)(sm + OFF_BV);

    const int tid = threadIdx.x;
    const int w = tid >> 5;
    const int lane = tid & 31;
    const int j = lane & 3;            // fragment quad-lane
    const int gID = lane >> 2;         // fragment group (0..7)
    const int r1 = gID, r2 = gID + 8;  // token rows covered by this thread

    // ---- weight prep: pre-packed bf16 fragment u64s ----
    // entry i: n = i%160, rr = i/160 = (term*2+kt)*4 + jj
    for (int i = tid; i < 2560; i += THREADS) {
        int n = i % 160, rr = i / 160;
        int jj = rr & 3, kt = (rr >> 2) & 1, term = rr >> 3;
        int d0 = kt * 16 + 2 * jj;
        const float* wr = (n < 128) ? (Wk + n * 32) : (Wv + (n - 128) * 32);
        float2 pa = make_float2(wr[d0], wr[d0 + 1]);
        float2 pb = make_float2(wr[d0 + 8], wr[d0 + 9]);
        unsigned lo32, hi32;
        if (term == 0) { lo32 = packhi(pa); hi32 = packhi(pb); }
        else           { lo32 = packlo(pa); hi32 = packlo(pb); }
        sB[rr * SB_STRIDE + n] = ((unsigned long long)hi32 << 32) | lo32;
    }
    for (int i = tid; i < 128; i += THREADS) {
        sBK[i] = bk[i];
        sGG[i] = g1[i] * g2[i];
    }
    if (tid < 32) sBV[tid] = bv[tid];
    __syncthreads();

    float* esf = (float*)(sm + OFF_ES) + w * 640;      // e stage, stride 40 f
    float* sQf = (float*)(sm + OFF_Q) + w * 2176;      // q stage, stride 136 f
    float* sGate = (float*)(sm + OFF_GATE) + w * 64;   // [r][h]
    const unsigned qA = su32(sQf);

    const int warpG = blockIdx.x * NWARPS + w;
    const int totW = NBLOCKS * NWARPS;
    const int nTiles = (nTok + TILE_M - 1) / TILE_M;

    const float EPS = 1.1920929e-07f;
    const float INV32 = 0.03125f;
    const float INVSQRT32 = 0.17677669529663687f;

    // ---- prologue: prefetch e for first tile ----
    float4 ep[4];
    if (warpG < nTiles) {
        int t0 = warpG * TILE_M;
#pragma unroll
        for (int it = 0; it < 4; it++) {
            int i = it * 32 + lane, r = i >> 3, c4 = i & 7;
            int row = min(t0 + r, nTok - 1);
            ep[it] = *(const float4*)(emb + (size_t)row * 32 + c4 * 4);
        }
    }

    for (int g = warpG; g < nTiles; g += totW) {
        const int t0 = g * TILE_M;

        // ---- 1. q -> smem via cp.async (16 x 16B per lane) ----
#pragma unroll
        for (int it = 0; it < 16; it++) {
            int i = it * 32 + lane, r = i >> 5, c = i & 31;
            int row = min(t0 + r, nTok - 1);
            cp16(qA + r * 544 + c * 16, hid + (size_t)row * 128 + c * 4);
        }
        asm volatile("cp.async.commit_group;");

        // ---- 2. e regs -> stage (zero pad rows) ----
#pragma unroll
        for (int it = 0; it < 4; it++) {
            int i = it * 32 + lane, r = i >> 3, c4 = i & 7;
            float4 v = (t0 + r < nTok) ? ep[it] : make_float4(0.f, 0.f, 0.f, 0.f);
            *(float4*)(esf + r * 40 + c4 * 4) = v;
        }
        __syncwarp();

        // ---- 3. A fragments (hi & lo) ----
        unsigned Ahi[2][4], Alo[2][4];
#pragma unroll
        for (int kt = 0; kt < 2; kt++) {
            int c0 = 16 * kt + 2 * j;
            float2 p0 = *(const float2*)(esf + r1 * 40 + c0);
            float2 p1 = *(const float2*)(esf + r2 * 40 + c0);
            float2 p2 = *(const float2*)(esf + r1 * 40 + c0 + 8);
            float2 p3 = *(const float2*)(esf + r2 * 40 + c0 + 8);
            Ahi[kt][0] = packhi(p0); Alo[kt][0] = packlo(p0);
            Ahi[kt][1] = packhi(p1); Alo[kt][1] = packlo(p1);
            Ahi[kt][2] = packhi(p2); Alo[kt][2] = packlo(p2);
            Ahi[kt][3] = packhi(p3); Alo[kt][3] = packlo(p3);
        }

        // ---- 4. prefetch e for next tile ----
        {
            int gn = g + totW;
            if (gn < nTiles) {
                int t0n = gn * TILE_M;
#pragma unroll
                for (int it = 0; it < 4; it++) {
                    int i = it * 32 + lane, r = i >> 3, c4 = i & 7;
                    int row = min(t0n + r, nTok - 1);
                    ep[it] = *(const float4*)(emb + (size_t)row * 32 + c4 * 4);
                }
            }
        }

        const unsigned long long* sBt = sB + (size_t)j * SB_STRIDE + gID;

        // ---- 5. value MMAs (n-tiles 16..19) ----
        float4 accV[4];
#pragma unroll
        for (int m = 0; m < 4; m++) accV[m] = make_float4(0.f, 0.f, 0.f, 0.f);
#pragma unroll
        for (int term = 0; term < 3; term++) {
            const unsigned (*Af)[4] = (term == 2) ? Alo : Ahi;
            const int bt = (term == 1) ? 1 : 0;
#pragma unroll
            for (int kt = 0; kt < 2; kt++) {
                const unsigned long long* bp = sBt + (bt * 8 + kt * 4) * SB_STRIDE + 128;
#pragma unroll
                for (int m = 0; m < 4; m++) {
                    unsigned long long b = bp[8 * m];
                    mma_bf16(accV[m], Af[kt], (unsigned)b, (unsigned)(b >> 32));
                }
            }
        }

        // ---- 6. q ready ----
        asm volatile("cp.async.wait_group 0;");
        __syncwarp();

        // ---- 7. heads: key MMAs + gate epilogue (acc reuse) ----
#pragma unroll 1
        for (int h = 0; h < HC; h++) {
            float4 accK[4];
#pragma unroll
            for (int m = 0; m < 4; m++) accK[m] = make_float4(0.f, 0.f, 0.f, 0.f);
#pragma unroll
            for (int term = 0; term < 3; term++) {
                const unsigned (*Af)[4] = (term == 2) ? Alo : Ahi;
                const int bt = (term == 1) ? 1 : 0;
#pragma unroll
                for (int kt = 0; kt < 2; kt++) {
                    const unsigned long long* bp =
                        sBt + (bt * 8 + kt * 4) * SB_STRIDE + 32 * h;
#pragma unroll
                    for (int m = 0; m < 4; m++) {
                        unsigned long long b = bp[8 * m];
                        mma_bf16(accK[m], Af[kt], (unsigned)b, (unsigned)(b >> 32));
                    }
                }
            }

            const float* bkh = sBK + h * 32 + 2 * j;
            const float* ggh = sGG + h * 32 + 2 * j;
            const float* q1p = sQf + r1 * 136 + h * 32 + 2 * j;
            const float* q2p = sQf + r2 * 136 + h * 32 + 2 * j;

            float kk1 = 0.f, qq1 = 0.f, kq1 = 0.f;
            float kk2 = 0.f, qq2 = 0.f, kq2 = 0.f;
#pragma unroll
            for (int m = 0; m < 4; m++) {
                float2 bkp = *(const float2*)(bkh + 8 * m);
                float2 ggp = *(const float2*)(ggh + 8 * m);
                float2 q1 = *(const float2*)(q1p + 8 * m);
                float2 q2 = *(const float2*)(q2p + 8 * m);
                float k0 = accK[m].x + bkp.x, k1 = accK[m].y + bkp.y;   // row r1
                float k2 = accK[m].z + bkp.x, k3 = accK[m].w + bkp.y;   // row r2
                kk1 += k0 * k0 + k1 * k1;
                kk2 += k2 * k2 + k3 * k3;
                qq1 += q1.x * q1.x + q1.y * q1.y;
                qq2 += q2.x * q2.x + q2.y * q2.y;
                kq1 += k0 * ggp.x * q1.x + k1 * ggp.y * q1.y;
                kq2 += k2 * ggp.x * q2.x + k3 * ggp.y * q2.y;
            }
            // 2-step butterfly across the 4 j-lanes (serves 8 token-rows/instr)
#pragma unroll
            for (int msk = 1; msk < 4; msk <<= 1) {
                kk1 += __shfl_xor_sync(0xffffffffu, kk1, msk);
                qq1 += __shfl_xor_sync(0xffffffffu, qq1, msk);
                kq1 += __shfl_xor_sync(0xffffffffu, kq1, msk);
                kk2 += __shfl_xor_sync(0xffffffffu, kk2, msk);
                qq2 += __shfl_xor_sync(0xffffffffu, qq2, msk);
                kq2 += __shfl_xor_sync(0xffffffffu, kq2, msk);
            }
            float rA = kq1 * rsqrtf(fmaf(kk1, INV32, EPS))
                           * rsqrtf(fmaf(qq1, INV32, EPS)) * INVSQRT32;
            float rB = kq2 * rsqrtf(fmaf(kk2, INV32, EPS))
                           * rsqrtf(fmaf(qq2, INV32, EPS)) * INVSQRT32;
            float aA = sqrtf(fmaxf(fabsf(rA), 1e-6f));
            aA = (rA > 0.f) ? aA : ((rA < 0.f) ? -aA : 0.f);
            float aB = sqrtf(fmaxf(fabsf(rB), 1e-6f));
            aB = (rB > 0.f) ? aB : ((rB < 0.f) ? -aB : 0.f);
            float gA = 1.0f / (1.0f + __expf(-aA));
            float gB = 1.0f / (1.0f + __expf(-aB));
            if (j == 0) {
                sGate[r1 * 4 + h] = gA;
                sGate[r2 * 4 + h] = gB;
            }
        }
        __syncwarp();

        // ---- 8. value + gate stores ----
        {
            float4 gA = *(const float4*)&sGate[r1 * 4];   // gates h0..3, row r1
            float4 gB = *(const float4*)&sGate[r2 * 4];
            const bool okA = (t0 + r1) < nTok;
            const bool okB = (t0 + r2) < nTok;
            float* oA = out + (size_t)(t0 + r1) * 128 + 2 * j;
            float* oB = out + (size_t)(t0 + r2) * 128 + 2 * j;
#pragma unroll
            for (int m = 0; m < 4; m++) {
                float2 bvp = *(const float2*)(sBV + 8 * m + 2 * j);
                float v0 = accV[m].x + bvp.x, v1 = accV[m].y + bvp.y;  // r1
                float v2 = accV[m].z + bvp.x, v3 = accV[m].w + bvp.y;  // r2
                const float gAh[4] = {gA.x, gA.y, gA.z, gA.w};
                const float gBh[4] = {gB.x, gB.y, gB.z, gB.w};
#pragma unroll
                for (int h = 0; h < 4; h++) {
                    if (okA)
                        *(float2*)(oA + h * 32 + 8 * m) =
                            make_float2(gAh[h] * v0, gAh[h] * v1);
                    if (okB)
                        *(float2*)(oB + h * 32 + 8 * m) =
                            make_float2(gBh[h] * v2, gBh[h] * v3);
                }
            }
        }
        __syncwarp();
    }
}

extern "C" void kernel_launch(void* const* d_in, const int* in_sizes, int n_in,
                              void* d_out, int out_size) {
    const float* emb = (const float*)d_in[0];
    const float* hid = (const float*)d_in[1];
    const float* Wv  = (const float*)d_in[2];
    const float* bv  = (const float*)d_in[3];
    const float* Wk  = (const float*)d_in[4];
    const float* bk  = (const float*)d_in[5];
    const float* g1  = (const float*)d_in[6];
    const float* g2  = (const float*)d_in[7];
    float* out = (float*)d_out;

    int nTok = in_sizes[0] / 32;

    cudaFuncSetAttribute(engram_gating_mma,
                         cudaFuncAttributeMaxDynamicSharedMemorySize, SMEM_TOTAL);

    engram_gating_mma<<<NBLOCKS, THREADS, SMEM_TOTAL>>>(
        emb, hid, Wv, bv, Wk, bk, g1, g2, out, nTok);
}